// round 16
// baseline (speedup 1.0000x reference)
#include <cuda_runtime.h>
#include <cuda_fp16.h>
#include <cstdint>

// UnionLayer via degree-4 minimax polynomial -> fp16 mma.sync GEMM.
//   -log(1-t) ~= c0 + c1 t + c2 t^2 + c3 t^3 + c4 t^4,  t = u*w in [0, 0.5]
//   c0 = 5.196e-5, c1 = 0.995072, c2 = 0.572809, c3 = -0.025378, c4 = 0.887357
//   S = 512*c0 + sum_n c_n (u^n . w^n);  con: y = 1/(1+S); dis: y = 1 - 1/(1+S)
// R16 = R15 compute structure + FRAGMENT-LAYOUT SCRATCH:
//   R15 was L1-wavefront bound (each mainloop LDG.64 touched 8 lines; L1=46%
//   invariant to instruction cuts). A prep kernel rewrites A/B as fp16 mma
//   fragments, 16B contiguous per (block, k16-unit, lane) -> the GEMM loads
//   4 LDG.128 x 512B contiguous per warp per unit = 4 wf each (8x fewer).
//   Also removes all cvt/FADD from the mainloop.
// Layouts:
//   AS[z][mb][uu][lane] : 16B = {(g,p0),(g+8,p0),(g,p1),(g+8,p1)} of u^1 halves
//       mb = row/16 (64), uu = d/16 (32), row value u = z ? x : 1-x
//   BS[z][uu][nbp][lane]: 16B = {(c0,p0),(c0,p1),(c1,p0),(c1,p1)}, c0 = nbp*16+g,
//       c1 = c0+8 (two n8 blocks per 16B)
// GEMM: grid (8,8,2), 256 thr, 8 warps = 4 m-slices x 2 d-halves, chains +
// software pipelining identical to R15. Epilogue S = c1*acc + 512*c0.

#define DDIM    512
#define NOUT    512
#define NCOLS   256
#define NTERMS  4
#define THREADS 256

// chain ratios r_n = c_{n+1}/c_n
#define R1   0.575646f
#define R2  -0.0443078f
#define R3 -34.9657f
// epilogue: S = C1E * acc + C0E
#define C1E  0.995072f
#define C0E  0.0266046f

__device__ uint4 AS[2 * 64 * 32 * 32];   // 2 MB   [z][mb][uu][lane]
__device__ uint4 BSg[2 * 32 * 16 * 32];  // 512 KB [z][uu][nbp][lane]

__global__ __launch_bounds__(256) void prep_kernel(
    const float* __restrict__ x,
    const float* __restrict__ Wcon,
    const float* __restrict__ Wdis)
{
    const int t = blockIdx.x * 256 + threadIdx.x;
    if (t < 131072) {
        // A: t = ((z*64 + mb)*32 + uu)*32 + l
        const int z  = t >> 16;
        const int rem = t & 65535;
        const int mb = rem >> 10;
        const int uu = (rem >> 5) & 31;
        const int l  = rem & 31;
        const int g  = l >> 2, t4 = l & 3;
        const int row = mb * 16 + g;
        const int d0  = uu * 16 + 2 * t4;
        float2 v00 = *reinterpret_cast<const float2*>(&x[row * DDIM + d0]);
        float2 v01 = *reinterpret_cast<const float2*>(&x[row * DDIM + d0 + 8]);
        float2 v10 = *reinterpret_cast<const float2*>(&x[(row + 8) * DDIM + d0]);
        float2 v11 = *reinterpret_cast<const float2*>(&x[(row + 8) * DDIM + d0 + 8]);
        if (z == 0) {
            v00.x = 1.0f - v00.x; v00.y = 1.0f - v00.y;
            v01.x = 1.0f - v01.x; v01.y = 1.0f - v01.y;
            v10.x = 1.0f - v10.x; v10.y = 1.0f - v10.y;
            v11.x = 1.0f - v11.x; v11.y = 1.0f - v11.y;
        }
        __half2 f[4];
        f[0] = __floats2half2_rn(v00.x, v00.y);   // (row,   p0) -> a0
        f[1] = __floats2half2_rn(v10.x, v10.y);   // (row+8, p0) -> a1
        f[2] = __floats2half2_rn(v01.x, v01.y);   // (row,   p1) -> a2
        f[3] = __floats2half2_rn(v11.x, v11.y);   // (row+8, p1) -> a3
        AS[t] = *reinterpret_cast<const uint4*>(f);
    } else if (t < 131072 + 32768) {
        // B: i = ((z*32 + uu)*16 + nbp)*32 + l
        const int i  = t - 131072;
        const int z  = i >> 14;
        const int rem = i & 16383;
        const int uu = rem >> 9;
        const int nbp = (rem >> 5) & 15;
        const int l  = rem & 31;
        const int g  = l >> 2, t4 = l & 3;
        const float* __restrict__ src = z ? Wdis : Wcon;
        const int c0 = nbp * 16 + g;
        const int d0 = uu * 16 + 2 * t4;
        float2 v00 = *reinterpret_cast<const float2*>(&src[c0 * DDIM + d0]);
        float2 v01 = *reinterpret_cast<const float2*>(&src[c0 * DDIM + d0 + 8]);
        float2 v10 = *reinterpret_cast<const float2*>(&src[(c0 + 8) * DDIM + d0]);
        float2 v11 = *reinterpret_cast<const float2*>(&src[(c0 + 8) * DDIM + d0 + 8]);
        __half2 f[4];
        f[0] = __floats2half2_rn(v00.x, v00.y);   // (c0, p0) -> b0 of nb even
        f[1] = __floats2half2_rn(v01.x, v01.y);   // (c0, p1) -> b1 of nb even
        f[2] = __floats2half2_rn(v10.x, v10.y);   // (c1, p0) -> b0 of nb odd
        f[3] = __floats2half2_rn(v11.x, v11.y);   // (c1, p1) -> b1 of nb odd
        BSg[i] = *reinterpret_cast<const uint4*>(f);
    }
}

__device__ __forceinline__ void mma16816(float* c, uint32_t a0, uint32_t a1,
                                         uint32_t a2, uint32_t a3,
                                         uint32_t b0, uint32_t b1) {
    asm volatile(
        "mma.sync.aligned.m16n8k16.row.col.f32.f16.f16.f32 "
        "{%0,%1,%2,%3}, {%4,%5,%6,%7}, {%8,%9}, {%0,%1,%2,%3};"
        : "+f"(c[0]), "+f"(c[1]), "+f"(c[2]), "+f"(c[3])
        : "r"(a0), "r"(a1), "r"(a2), "r"(a3), "r"(b0), "r"(b1));
}

__device__ __forceinline__ uint32_t h2u(__half2 h) {
    return *reinterpret_cast<uint32_t*>(&h);
}
__device__ __forceinline__ __half2 u2h(uint32_t u) {
    return *reinterpret_cast<__half2*>(&u);
}

__global__ __launch_bounds__(THREADS) void union_mma_kernel(
    float* __restrict__ out)
{
    __shared__ float red[4][32][32];   // d-half-1 partials (16 KB)

    const int tid  = threadIdx.x;
    const int wid  = tid >> 5;
    const int lane = tid & 31;
    const int g    = lane >> 2;
    const int t4   = lane & 3;
    const int msl  = wid & 3;          // m-slice (32 rows)
    const int dh   = wid >> 2;         // d-half 0/1
    const int bn0  = blockIdx.x * 32;
    const int bm0  = blockIdx.y * 128;
    const int z    = blockIdx.z;       // 0 = con, 1 = dis

    // A fragment pointers: mb0 = (bm0 + msl*32)/16, stride per mb = 1024 uint4
    const int mb0 = (bm0 + msl * 32) >> 4;
    const uint4* __restrict__ aP0 = &AS[((z * 64 + mb0) * 32) * 32 + lane];
    const uint4* __restrict__ aP1 = aP0 + 1024;          // mb0 + 1
    // B fragment pointer: nbp0 = bn0/16; per uu stride = 512, nbp stride = 32
    const int nbp0 = bn0 >> 4;
    const uint4* __restrict__ bP = &BSg[(z * 32 * 16 + nbp0) * 32 + lane];

    float acc[2][4][4];
#pragma unroll
    for (int mt = 0; mt < 2; mt++)
#pragma unroll
        for (int nt = 0; nt < 4; nt++)
#pragma unroll
            for (int c = 0; c < 4; c++) acc[mt][nt][c] = 0.0f;

    const float kf[NTERMS] = {0.f, R1, R2, R3};
    const int uubase = dh * 16;

    // staged fragment loads: [0]=A mb0, [1]=A mb1, [2]=B nbp0, [3]=B nbp1
    uint4 st[2][4];
    st[0][0] = aP0[uubase * 32];
    st[0][1] = aP1[uubase * 32];
    st[0][2] = bP[uubase * 512];
    st[0][3] = bP[uubase * 512 + 32];

#pragma unroll 1
    for (int u = 0; u < 16; u++) {
        const int b = u & 1;

        // ---- unpack staged fragments into chain buffers ----
        __half2 baseA[4][2], baseB[4][2], curA[2][4][2], curB[2][4][2];
        {
            const uint4 A0 = st[b][0], A1 = st[b][1];
            const uint4 B0 = st[b][2], B1 = st[b][3];
            baseA[0][0] = u2h(A0.x); baseA[1][0] = u2h(A0.y);
            baseA[0][1] = u2h(A0.z); baseA[1][1] = u2h(A0.w);
            baseA[2][0] = u2h(A1.x); baseA[3][0] = u2h(A1.y);
            baseA[2][1] = u2h(A1.z); baseA[3][1] = u2h(A1.w);
            baseB[0][0] = u2h(B0.x); baseB[0][1] = u2h(B0.y);
            baseB[1][0] = u2h(B0.z); baseB[1][1] = u2h(B0.w);
            baseB[2][0] = u2h(B1.x); baseB[2][1] = u2h(B1.y);
            baseB[3][0] = u2h(B1.z); baseB[3][1] = u2h(B1.w);
#pragma unroll
            for (int r = 0; r < 4; r++)
#pragma unroll
                for (int p = 0; p < 2; p++) {
                    curA[0][r][p] = baseA[r][p];
                    curB[0][r][p] = baseB[r][p];
                }
        }

        // ---- prefetch next unit's fragments ----
        if (u + 1 < 16) {
            const int uu = uubase + u + 1;
            st[b ^ 1][0] = aP0[uu * 32];
            st[b ^ 1][1] = aP1[uu * 32];
            st[b ^ 1][2] = bP[uu * 512];
            st[b ^ 1][3] = bP[uu * 512 + 32];
        }

        // ---- 4 poly terms, software-pipelined: chain(n+1) BEFORE mma(n) ----
#pragma unroll
        for (int n = 0; n < NTERMS; n++) {
            const int cb = n & 1, nb = (n + 1) & 1;
            if (n + 1 < NTERMS) {
                const __half2 kfh = __float2half2_rn(kf[n + 1]);
#pragma unroll
                for (int r = 0; r < 4; r++)
#pragma unroll
                    for (int p = 0; p < 2; p++) {
                        curA[nb][r][p] = __hmul2(curA[cb][r][p], baseA[r][p]);
                        __half2 bb     = __hmul2(baseB[r][p], kfh);
                        curB[nb][r][p] = __hmul2(curB[cb][r][p], bb);
                    }
            }
#pragma unroll
            for (int mt = 0; mt < 2; mt++) {
                uint32_t a0 = h2u(curA[cb][mt * 2 + 0][0]);
                uint32_t a1 = h2u(curA[cb][mt * 2 + 1][0]);
                uint32_t a2 = h2u(curA[cb][mt * 2 + 0][1]);
                uint32_t a3 = h2u(curA[cb][mt * 2 + 1][1]);
#pragma unroll
                for (int nt = 0; nt < 4; nt++) {
                    mma16816(acc[mt][nt], a0, a1, a2, a3,
                             h2u(curB[cb][nt][0]), h2u(curB[cb][nt][1]));
                }
            }
        }
    }

    // ---- merge d-halves: half 1 stores, half 0 adds + epilogue ----
    if (dh == 1) {
#pragma unroll
        for (int mt = 0; mt < 2; mt++)
#pragma unroll
            for (int hh = 0; hh < 2; hh++) {
                int r = mt * 16 + hh * 8 + g;
#pragma unroll
                for (int nt = 0; nt < 4; nt++) {
                    *reinterpret_cast<float2*>(&red[msl][r][nt * 8 + 2 * t4]) =
                        make_float2(acc[mt][nt][hh * 2 + 0], acc[mt][nt][hh * 2 + 1]);
                }
            }
    }
    __syncthreads();

    if (dh == 0) {
#pragma unroll
        for (int mt = 0; mt < 2; mt++) {
#pragma unroll
            for (int hh = 0; hh < 2; hh++) {
                int r = mt * 16 + hh * 8 + g;
                int m = bm0 + msl * 32 + r;
#pragma unroll
                for (int nt = 0; nt < 4; nt++) {
                    float2 o = *reinterpret_cast<const float2*>(&red[msl][r][nt * 8 + 2 * t4]);
                    float S0 = fmaf(C1E, acc[mt][nt][hh * 2 + 0] + o.x, C0E);
                    float S1 = fmaf(C1E, acc[mt][nt][hh * 2 + 1] + o.y, C0E);
                    float y0 = 1.0f / (1.0f + S0);
                    float y1 = 1.0f / (1.0f + S1);
                    if (z) { y0 = 1.0f - y0; y1 = 1.0f - y1; }
                    int col = bn0 + nt * 8 + 2 * t4;
                    *reinterpret_cast<float2*>(&out[m * NOUT + z * NCOLS + col]) =
                        make_float2(y0, y1);
                }
            }
        }
    }
}

extern "C" void kernel_launch(void* const* d_in, const int* in_sizes, int n_in,
                              void* d_out, int out_size)
{
    const float* x    = (const float*)d_in[0];
    const float* Wcon = (const float*)d_in[1];
    const float* Wdis = (const float*)d_in[2];
    float* out = (float*)d_out;

    prep_kernel<<<640, 256>>>(x, Wcon, Wdis);    // 163840 threads

    dim3 grid(NCOLS / 32, 1024 / 128, 2);        // (8, 8, 2) = 128 CTAs
    union_mma_kernel<<<grid, THREADS>>>(out);
}

// round 17
// speedup vs baseline: 1.2405x; 1.2405x over previous
#include <cuda_runtime.h>
#include <cuda_fp16.h>
#include <cstdint>

// UnionLayer via degree-4 minimax polynomial -> fp16 mma.sync GEMM.
//   -log(1-t) ~= c0 + c1 t + c2 t^2 + c3 t^3 + c4 t^4,  t = u*w in [0, 0.5]
//   c0 = 5.196e-5, c1 = 0.995072, c2 = 0.572809, c3 = -0.025378, c4 = 0.887357
//   S = 512*c0 + sum_n c_n (u^n . w^n);  con: y = 1/(1+S); dis: y = 1 - 1/(1+S)
// R17 = R16 (fragment-layout scratch, 8x fewer L1 wavefronts) with the staging
// SPILL FIXED: R16's st[2][4] was runtime-indexed under #pragma unroll 1 ->
// local memory (regs fell to 78, issue 17%). Now: #pragma unroll 2 makes
// b = u&1 compile-time (registers), and prefetch distance is 2 units so L2
// latency (~250cyc) is covered by ~2 units of compute.
// Layouts (from prep):
//   AS[z][mb][uu][lane] : 16B = {(g,p0),(g+8,p0),(g,p1),(g+8,p1)} of u halves
//   BSg[z][uu][nbp][lane]: 16B = {(c0,p0),(c0,p1),(c1,p0),(c1,p1)}, c1 = c0+8
// GEMM: grid (8,8,2), 256 thr, 8 warps = 4 m-slices x 2 d-halves; chains +
// term-level software pipelining identical to R15. Epilogue S = c1*acc + 512c0.

#define DDIM    512
#define NOUT    512
#define NCOLS   256
#define NTERMS  4
#define THREADS 256

// chain ratios r_n = c_{n+1}/c_n
#define R1   0.575646f
#define R2  -0.0443078f
#define R3 -34.9657f
// epilogue: S = C1E * acc + C0E
#define C1E  0.995072f
#define C0E  0.0266046f

__device__ uint4 AS[2 * 64 * 32 * 32];   // 2 MB   [z][mb][uu][lane]
__device__ uint4 BSg[2 * 32 * 16 * 32];  // 512 KB [z][uu][nbp][lane]

__global__ __launch_bounds__(256) void prep_kernel(
    const float* __restrict__ x,
    const float* __restrict__ Wcon,
    const float* __restrict__ Wdis)
{
    const int t = blockIdx.x * 256 + threadIdx.x;
    if (t < 131072) {
        // A: t = ((z*64 + mb)*32 + uu)*32 + l
        const int z  = t >> 16;
        const int rem = t & 65535;
        const int mb = rem >> 10;
        const int uu = (rem >> 5) & 31;
        const int l  = rem & 31;
        const int g  = l >> 2, t4 = l & 3;
        const int row = mb * 16 + g;
        const int d0  = uu * 16 + 2 * t4;
        float2 v00 = *reinterpret_cast<const float2*>(&x[row * DDIM + d0]);
        float2 v01 = *reinterpret_cast<const float2*>(&x[row * DDIM + d0 + 8]);
        float2 v10 = *reinterpret_cast<const float2*>(&x[(row + 8) * DDIM + d0]);
        float2 v11 = *reinterpret_cast<const float2*>(&x[(row + 8) * DDIM + d0 + 8]);
        if (z == 0) {
            v00.x = 1.0f - v00.x; v00.y = 1.0f - v00.y;
            v01.x = 1.0f - v01.x; v01.y = 1.0f - v01.y;
            v10.x = 1.0f - v10.x; v10.y = 1.0f - v10.y;
            v11.x = 1.0f - v11.x; v11.y = 1.0f - v11.y;
        }
        __half2 f[4];
        f[0] = __floats2half2_rn(v00.x, v00.y);   // (row,   p0) -> a0
        f[1] = __floats2half2_rn(v10.x, v10.y);   // (row+8, p0) -> a1
        f[2] = __floats2half2_rn(v01.x, v01.y);   // (row,   p1) -> a2
        f[3] = __floats2half2_rn(v11.x, v11.y);   // (row+8, p1) -> a3
        AS[t] = *reinterpret_cast<const uint4*>(f);
    } else if (t < 131072 + 32768) {
        // B: i = ((z*32 + uu)*16 + nbp)*32 + l
        const int i  = t - 131072;
        const int z  = i >> 14;
        const int rem = i & 16383;
        const int uu = rem >> 9;
        const int nbp = (rem >> 5) & 15;
        const int l  = rem & 31;
        const int g  = l >> 2, t4 = l & 3;
        const float* __restrict__ src = z ? Wdis : Wcon;
        const int c0 = nbp * 16 + g;
        const int d0 = uu * 16 + 2 * t4;
        float2 v00 = *reinterpret_cast<const float2*>(&src[c0 * DDIM + d0]);
        float2 v01 = *reinterpret_cast<const float2*>(&src[c0 * DDIM + d0 + 8]);
        float2 v10 = *reinterpret_cast<const float2*>(&src[(c0 + 8) * DDIM + d0]);
        float2 v11 = *reinterpret_cast<const float2*>(&src[(c0 + 8) * DDIM + d0 + 8]);
        __half2 f[4];
        f[0] = __floats2half2_rn(v00.x, v00.y);   // (c0, p0) -> b0 of nb even
        f[1] = __floats2half2_rn(v01.x, v01.y);   // (c0, p1) -> b1 of nb even
        f[2] = __floats2half2_rn(v10.x, v10.y);   // (c1, p0) -> b0 of nb odd
        f[3] = __floats2half2_rn(v11.x, v11.y);   // (c1, p1) -> b1 of nb odd
        BSg[i] = *reinterpret_cast<const uint4*>(f);
    }
}

__device__ __forceinline__ void mma16816(float* c, uint32_t a0, uint32_t a1,
                                         uint32_t a2, uint32_t a3,
                                         uint32_t b0, uint32_t b1) {
    asm volatile(
        "mma.sync.aligned.m16n8k16.row.col.f32.f16.f16.f32 "
        "{%0,%1,%2,%3}, {%4,%5,%6,%7}, {%8,%9}, {%0,%1,%2,%3};"
        : "+f"(c[0]), "+f"(c[1]), "+f"(c[2]), "+f"(c[3])
        : "r"(a0), "r"(a1), "r"(a2), "r"(a3), "r"(b0), "r"(b1));
}

__device__ __forceinline__ uint32_t h2u(__half2 h) {
    return *reinterpret_cast<uint32_t*>(&h);
}
__device__ __forceinline__ __half2 u2h(uint32_t u) {
    return *reinterpret_cast<__half2*>(&u);
}

__global__ __launch_bounds__(THREADS) void union_mma_kernel(
    float* __restrict__ out)
{
    __shared__ float red[4][32][32];   // d-half-1 partials (16 KB)

    const int tid  = threadIdx.x;
    const int wid  = tid >> 5;
    const int lane = tid & 31;
    const int g    = lane >> 2;
    const int t4   = lane & 3;
    const int msl  = wid & 3;          // m-slice (32 rows)
    const int dh   = wid >> 2;         // d-half 0/1
    const int bn0  = blockIdx.x * 32;
    const int bm0  = blockIdx.y * 128;
    const int z    = blockIdx.z;       // 0 = con, 1 = dis

    // A fragment pointers: mb0 = (bm0 + msl*32)/16, stride per mb = 1024 uint4
    const int mb0 = (bm0 + msl * 32) >> 4;
    const uint4* __restrict__ aP0 = &AS[((z * 64 + mb0) * 32) * 32 + lane];
    const uint4* __restrict__ aP1 = aP0 + 1024;          // mb0 + 1
    // B fragment pointer: nbp0 = bn0/16; per uu stride = 512, nbp stride = 32
    const int nbp0 = bn0 >> 4;
    const uint4* __restrict__ bP = &BSg[(z * 32 * 16 + nbp0) * 32 + lane];

    float acc[2][4][4];
#pragma unroll
    for (int mt = 0; mt < 2; mt++)
#pragma unroll
        for (int nt = 0; nt < 4; nt++)
#pragma unroll
            for (int c = 0; c < 4; c++) acc[mt][nt][c] = 0.0f;

    const float kf[NTERMS] = {0.f, R1, R2, R3};
    const int uubase = dh * 16;

    // staging double buffer; statically indexed under #pragma unroll 2
    uint4 st[2][4];
    st[0][0] = aP0[(uubase + 0) * 32];
    st[0][1] = aP1[(uubase + 0) * 32];
    st[0][2] = bP[(uubase + 0) * 512];
    st[0][3] = bP[(uubase + 0) * 512 + 32];
    st[1][0] = aP0[(uubase + 1) * 32];
    st[1][1] = aP1[(uubase + 1) * 32];
    st[1][2] = bP[(uubase + 1) * 512];
    st[1][3] = bP[(uubase + 1) * 512 + 32];

#pragma unroll 2
    for (int u = 0; u < 16; u++) {
        const int b = u & 1;           // compile-time under unroll 2

        // ---- unpack staged fragments into chain buffers ----
        __half2 baseA[4][2], baseB[4][2], curA[2][4][2], curB[2][4][2];
        {
            const uint4 A0 = st[b][0], A1 = st[b][1];
            const uint4 B0 = st[b][2], B1 = st[b][3];
            baseA[0][0] = u2h(A0.x); baseA[1][0] = u2h(A0.y);
            baseA[0][1] = u2h(A0.z); baseA[1][1] = u2h(A0.w);
            baseB[0][0] = u2h(B0.x); baseB[0][1] = u2h(B0.y);
            baseB[1][0] = u2h(B0.z); baseB[1][1] = u2h(B0.w);
            baseA[2][0] = u2h(A1.x); baseA[3][0] = u2h(A1.y);
            baseA[2][1] = u2h(A1.z); baseA[3][1] = u2h(A1.w);
            baseB[2][0] = u2h(B1.x); baseB[2][1] = u2h(B1.y);
            baseB[3][0] = u2h(B1.z); baseB[3][1] = u2h(B1.w);
#pragma unroll
            for (int r = 0; r < 4; r++)
#pragma unroll
                for (int p = 0; p < 2; p++) {
                    curA[0][r][p] = baseA[r][p];
                    curB[0][r][p] = baseB[r][p];
                }
        }

        // ---- prefetch unit u+2 into the buffer just consumed ----
        if (u + 2 < 16) {
            const int uu = uubase + u + 2;
            st[b][0] = aP0[uu * 32];
            st[b][1] = aP1[uu * 32];
            st[b][2] = bP[uu * 512];
            st[b][3] = bP[uu * 512 + 32];
        }

        // ---- 4 poly terms, software-pipelined: chain(n+1) BEFORE mma(n) ----
#pragma unroll
        for (int n = 0; n < NTERMS; n++) {
            const int cb = n & 1, nb = (n + 1) & 1;
            if (n + 1 < NTERMS) {
                const __half2 kfh = __float2half2_rn(kf[n + 1]);
#pragma unroll
                for (int r = 0; r < 4; r++)
#pragma unroll
                    for (int p = 0; p < 2; p++) {
                        curA[nb][r][p] = __hmul2(curA[cb][r][p], baseA[r][p]);
                        __half2 bb     = __hmul2(baseB[r][p], kfh);
                        curB[nb][r][p] = __hmul2(curB[cb][r][p], bb);
                    }
            }
#pragma unroll
            for (int mt = 0; mt < 2; mt++) {
                uint32_t a0 = h2u(curA[cb][mt * 2 + 0][0]);
                uint32_t a1 = h2u(curA[cb][mt * 2 + 1][0]);
                uint32_t a2 = h2u(curA[cb][mt * 2 + 0][1]);
                uint32_t a3 = h2u(curA[cb][mt * 2 + 1][1]);
#pragma unroll
                for (int nt = 0; nt < 4; nt++) {
                    mma16816(acc[mt][nt], a0, a1, a2, a3,
                             h2u(curB[cb][nt][0]), h2u(curB[cb][nt][1]));
                }
            }
        }
    }

    // ---- merge d-halves: half 1 stores, half 0 adds + epilogue ----
    if (dh == 1) {
#pragma unroll
        for (int mt = 0; mt < 2; mt++)
#pragma unroll
            for (int hh = 0; hh < 2; hh++) {
                int r = mt * 16 + hh * 8 + g;
#pragma unroll
                for (int nt = 0; nt < 4; nt++) {
                    *reinterpret_cast<float2*>(&red[msl][r][nt * 8 + 2 * t4]) =
                        make_float2(acc[mt][nt][hh * 2 + 0], acc[mt][nt][hh * 2 + 1]);
                }
            }
    }
    __syncthreads();

    if (dh == 0) {
#pragma unroll
        for (int mt = 0; mt < 2; mt++) {
#pragma unroll
            for (int hh = 0; hh < 2; hh++) {
                int r = mt * 16 + hh * 8 + g;
                int m = bm0 + msl * 32 + r;
#pragma unroll
                for (int nt = 0; nt < 4; nt++) {
                    float2 o = *reinterpret_cast<const float2*>(&red[msl][r][nt * 8 + 2 * t4]);
                    float S0 = fmaf(C1E, acc[mt][nt][hh * 2 + 0] + o.x, C0E);
                    float S1 = fmaf(C1E, acc[mt][nt][hh * 2 + 1] + o.y, C0E);
                    float y0 = 1.0f / (1.0f + S0);
                    float y1 = 1.0f / (1.0f + S1);
                    if (z) { y0 = 1.0f - y0; y1 = 1.0f - y1; }
                    int col = bn0 + nt * 8 + 2 * t4;
                    *reinterpret_cast<float2*>(&out[m * NOUT + z * NCOLS + col]) =
                        make_float2(y0, y1);
                }
            }
        }
    }
}

extern "C" void kernel_launch(void* const* d_in, const int* in_sizes, int n_in,
                              void* d_out, int out_size)
{
    const float* x    = (const float*)d_in[0];
    const float* Wcon = (const float*)d_in[1];
    const float* Wdis = (const float*)d_in[2];
    float* out = (float*)d_out;

    prep_kernel<<<640, 256>>>(x, Wcon, Wdis);    // 163840 threads

    dim3 grid(NCOLS / 32, 1024 / 128, 2);        // (8, 8, 2) = 128 CTAs
    union_mma_kernel<<<grid, THREADS>>>(out);
}